// round 15
// baseline (speedup 1.0000x reference)
#include <cuda_runtime.h>
#include <cuda_fp16.h>

// Problem dims (fixed)
#define Bv 4
#define Nv 256
#define Dv 128
#define Mv 128
#define Cv 128
#define ROWS 1024

// Scratch (allocation-free: __device__ globals)
__device__ unsigned g_pi_h[ROWS * 64];  // fp16x2-packed 0.5*(h@W1a + b1), m-pairs
__device__ unsigned g_pj_h[ROWS * 64];  // fp16x2-packed 0.5*(h@W1b)
__device__ float g_S0[ROWS * Mv];       // partial silu sum, j in [0,128)
__device__ float g_S1[ROWS * Mv];       // partial silu sum, j in [128,256)
__device__ float g_amask[ROWS];         // sum_{j!=i} adj
__device__ float g_denom[ROWS];         // max(sum_j adj, 1)

typedef unsigned long long ull;

// ---------------- packed f32x2 helpers ----------------
__device__ __forceinline__ ull pk2(float v) {
    ull r; asm("mov.b64 %0, {%1,%1};" : "=l"(r) : "f"(v)); return r;
}
__device__ __forceinline__ ull pkab(float a, float b) {
    ull r; asm("mov.b64 %0, {%1,%2};" : "=l"(r) : "f"(a), "f"(b)); return r;
}
__device__ __forceinline__ void fma2(ull& d, ull a, ull b) {
    asm("fma.rn.f32x2 %0, %1, %2, %0;" : "+l"(d) : "l"(a), "l"(b));
}
__device__ __forceinline__ ull add2(ull a, ull b) {
    ull r; asm("add.rn.f32x2 %0, %1, %2;" : "=l"(r) : "l"(a), "l"(b)); return r;
}
__device__ __forceinline__ void upk2(ull v, float& lo, float& hi) {
    asm("mov.b64 {%0,%1}, %2;" : "=f"(lo), "=f"(hi) : "l"(v));
}
__device__ __forceinline__ float tanh_ap(float x) {
    float t; asm("tanh.approx.f32 %0, %1;" : "=f"(t) : "f"(x)); return t;
}
// silu(2*xh) where xh = x/2:  xh*(1+tanh(xh))  [f32, used in k_post only]
__device__ __forceinline__ float silu_h(float xh) {
    return fmaf(xh, tanh_ap(xh), xh);
}

// ---------------- fp16x2 helpers ----------------
__device__ __forceinline__ unsigned f2_to_h2(float lo, float hi) {
    unsigned r;  // PTX packs first source into HIGH half
    asm("cvt.rn.f16x2.f32 %0, %1, %2;" : "=r"(r) : "f"(hi), "f"(lo));
    return r;
}
__device__ __forceinline__ unsigned hadd2(unsigned a, unsigned b) {
    unsigned r; asm("add.f16x2 %0, %1, %2;" : "=r"(r) : "r"(a), "r"(b)); return r;
}
__device__ __forceinline__ unsigned hfma2(unsigned a, unsigned b, unsigned c) {
    unsigned r; asm("fma.rn.f16x2 %0, %1, %2, %3;" : "=r"(r) : "r"(a), "r"(b), "r"(c)); return r;
}
__device__ __forceinline__ unsigned tanh_h2(unsigned x) {
    unsigned r; asm("tanh.approx.f16x2 %0, %1;" : "=r"(r) : "r"(x)); return r;
}
__device__ __forceinline__ void h2_to_f2(unsigned h, float& lo, float& hi) {
    asm("{ .reg .f16 l, u;\n\t"
        "mov.b32 {l, u}, %2;\n\t"
        "cvt.f32.f16 %0, l;\n\t"
        "cvt.f32.f16 %1, u; }"
        : "=f"(lo), "=f"(hi) : "r"(h));
}
// half-scaled silu on a f16x2 pair -> two f32:  s = x*tanh(x)+x
__device__ __forceinline__ void silu_h2f(unsigned x, float& lo, float& hi) {
    unsigned t = tanh_h2(x);
    unsigned s = hfma2(x, t, x);
    h2_to_f2(s, lo, hi);
}

// ---------------------------------------------------------------------------
// K1: pre-GEMM, k-split 4, 4 rows/block. (1024x128)@(128x256), W=[W1a|W1b].
// 256 blocks x 256 thr. Outputs fp16x2-packed pi/pj (pre-scaled by 0.5).
// ---------------------------------------------------------------------------
__global__ __launch_bounds__(256) void k_pre(const float* __restrict__ h,
                                             const float* __restrict__ W1a,
                                             const float* __restrict__ W1b,
                                             const float* __restrict__ b1)
{
    __shared__ ull sH[4][Dv];        // pk2-duplicated h, 4 rows (4 KB)
    __shared__ ull sP[4][4][128];    // [kseg][row][slot] partials (16 KB)

    const int tid  = threadIdx.x;
    const int row0 = blockIdx.x << 2;

    #pragma unroll
    for (int it = 0; it < 2; ++it) {
        const int idx = (it << 8) + tid;
        sH[idx >> 7][idx & 127] = pk2(__ldg(h + (row0 + (idx >> 7)) * Dv + (idx & 127)));
    }
    __syncthreads();

    const int kseg = tid >> 6;         // 0..3
    const int q    = tid & 63;         // colquad
    const int c    = q << 2;           // col 0..252
    const float* __restrict__ Wp = (c < 128) ? (W1a + c) : (W1b + (c - 128));
    const int k0 = kseg << 5;

    ull acc[4][2] = {};
    #pragma unroll 8
    for (int kk = 0; kk < 32; ++kk) {
        const int k = k0 + kk;
        ulonglong2 w = __ldg((const ulonglong2*)(Wp + k * Mv));
        #pragma unroll
        for (int r = 0; r < 4; ++r) {
            ull hr = sH[r][k];
            fma2(acc[r][0], hr, w.x);
            fma2(acc[r][1], hr, w.y);
        }
    }
    #pragma unroll
    for (int r = 0; r < 4; ++r) {
        sP[kseg][r][q]      = acc[r][0];
        sP[kseg][r][64 + q] = acc[r][1];
    }
    __syncthreads();

    // reduce: 512 units = 4 rows x 128 col-pairs; convert to fp16x2 and store
    #pragma unroll
    for (int it = 0; it < 2; ++it) {
        const int o  = (it << 8) + tid;
        const int r  = o >> 7;
        const int cp = o & 127;
        const int qq = cp >> 1;
        const int sl = (cp & 1) ? (64 + qq) : qq;
        ull s = add2(add2(sP[0][r][sl], sP[1][r][sl]),
                     add2(sP[2][r][sl], sP[3][r][sl]));
        float v0, v1; upk2(s, v0, v1);
        const int cc  = cp << 1;
        const int row = row0 + r;
        if (cc < 128) {
            float2 bb = __ldg((const float2*)(b1 + cc));
            g_pi_h[row * 64 + (cc >> 1)] =
                f2_to_h2(0.5f * (v0 + bb.x), 0.5f * (v1 + bb.y));
        } else {
            g_pj_h[row * 64 + ((cc - 128) >> 1)] =
                f2_to_h2(0.5f * v0, 0.5f * v1);
        }
    }
}

// ---------------------------------------------------------------------------
// K2: pairwise silu sum, fp16 math + fp32 accumulate.
// Block = (b, j-half) x 8 i-rows. 256 blocks x 256 thr. Warp = one i-row,
// lane owns 4 m's = 2 f16x2 units. pj tile (128 j x 64 pairs = 32 KB) in smem.
// One tanh.f16x2 per 2 elements -> MUFU floor halved vs f32 path.
// ---------------------------------------------------------------------------
__global__ __launch_bounds__(256) void k_main(const float* __restrict__ adj)
{
    __shared__ unsigned sPj[128][64];   // [j_local][m-pair] fp16x2 (32 KB)

    const int tid   = threadIdx.x;
    const int wid   = tid >> 5;
    const int lane  = tid & 31;
    const int combo = blockIdx.x >> 5;             // 0..7 : b*2 + jh
    const int blkc  = blockIdx.x & 31;             // 0..31
    const int b     = combo >> 1;
    const int jh    = combo & 1;
    const int i     = (blkc << 3) + wid;           // 0..255
    const int ig    = (b << 8) + i;
    const int j0    = jh << 7;
    const float* __restrict__ adjr = adj + (size_t)ig * Nv;

    // stage pj tile: contiguous 8192 uints -> flat uint4 copy, 8 iters
    {
        const uint4* __restrict__ src =
            (const uint4*)(g_pj_h + ((size_t)((b << 8) + j0)) * 64);
        uint4* dst = (uint4*)sPj;
        #pragma unroll
        for (int it = 0; it < 8; ++it)
            dst[(it << 8) + tid] = __ldg(src + (it << 8) + tid);
    }

    const float aii = __ldg(adjr + i);

    if (jh == 0) {      // one block per (b, i-group) does the adj reductions
        float4 s0 = __ldg((const float4*)adjr + lane);
        float4 s1 = __ldg((const float4*)adjr + 32 + lane);
        float rs = ((s0.x+s0.y)+(s0.z+s0.w)) + ((s1.x+s1.y)+(s1.z+s1.w));
        #pragma unroll
        for (int o = 16; o; o >>= 1) rs += __shfl_xor_sync(0xffffffffu, rs, o);
        if (lane == 0) {
            g_denom[ig] = fmaxf(rs, 1.0f);
            g_amask[ig] = rs - aii;
        }
    }

    const uint2 pih = *(const uint2*)(g_pi_h + ig * 64 + (lane << 1));
    __syncthreads();

    ull acc0 = 0, acc1 = 0;
    #pragma unroll 4
    for (int j = 0; j < 128; j += 4) {
        float4 av = __ldg((const float4*)adjr + ((j0 + j) >> 2));  // uniform
        #pragma unroll
        for (int t = 0; t < 4; ++t) {
            float a = (t == 0) ? av.x : (t == 1) ? av.y : (t == 2) ? av.z : av.w;
            uint2 p = *(const uint2*)&sPj[j + t][lane << 1];
            float l0, h0, l1, h1;
            silu_h2f(hadd2(pih.x, p.x), l0, h0);
            silu_h2f(hadd2(pih.y, p.y), l1, h1);
            ull ap = pk2(a);
            fma2(acc0, ap, pkab(l0, h0));
            fma2(acc1, ap, pkab(l1, h1));
        }
    }

    // subtract diagonal if i falls in this block's j-range
    if ((i >> 7) == jh) {
        uint2 p = *(const uint2*)&sPj[i & 127][lane << 1];
        float l0, h0, l1, h1;
        silu_h2f(hadd2(pih.x, p.x), l0, h0);
        silu_h2f(hadd2(pih.y, p.y), l1, h1);
        ull ap = pk2(-aii);
        fma2(acc0, ap, pkab(l0, h0));
        fma2(acc1, ap, pkab(l1, h1));
    }

    float* dst = (jh == 0) ? g_S0 : g_S1;
    *(ull*)(dst + ig * Mv + (lane << 2))     = acc0;
    *(ull*)(dst + ig * Mv + (lane << 2) + 2) = acc1;
}

// ---------------------------------------------------------------------------
// K3: chained GEMM epilogue. 256 blocks x 256 thr, 4 rows/block.
// 4-way k-split; thread does 4 rows x 1 col-pair (f32x2 straight from gmem).
// ---------------------------------------------------------------------------
__global__ __launch_bounds__(256) void k_post(const float* __restrict__ W2,  const float* __restrict__ b2,
                                              const float* __restrict__ Wc1, const float* __restrict__ bc1,
                                              const float* __restrict__ Wc2, const float* __restrict__ bc2,
                                              float* __restrict__ out)
{
    __shared__ ull sIn[4][Mv];      // duplicated f32x2 packs of current rows (4 KB)
    __shared__ ull sP[4][4][64];    // k-split partial accumulators (8 KB)

    const int tid  = threadIdx.x;
    const int row0 = blockIdx.x << 2;
    const int kseg = tid >> 6;          // 0..3
    const int cp   = tid & 63;          // col pair
    const int rrow = tid >> 6;          // reduce: output row 0..3
    const int rc   = (tid & 63) << 1;   // reduce: output col (even)

    #pragma unroll
    for (int it = 0; it < 2; ++it) {
        const int idx = (it << 8) + tid;        // 0..511
        sIn[idx >> 7][idx & 127] =
            pk2(__ldg(g_S0 + row0 * Mv + idx) + __ldg(g_S1 + row0 * Mv + idx));
    }
    __syncthreads();

    #pragma unroll 1
    for (int phase = 0; phase < 3; ++phase) {
        const float* W = (phase == 0) ? W2 : (phase == 1) ? Wc1 : Wc2;
        ull a0 = 0, a1 = 0, a2 = 0, a3 = 0;
        const ull* __restrict__ Wp = (const ull*)W + cp;
        #pragma unroll 8
        for (int kk = 0; kk < 32; ++kk) {
            const int k = (kseg << 5) + kk;
            ull wp = __ldg(Wp + (k << 6));
            fma2(a0, sIn[0][k], wp);
            fma2(a1, sIn[1][k], wp);
            fma2(a2, sIn[2][k], wp);
            fma2(a3, sIn[3][k], wp);
        }
        sP[kseg][0][cp] = a0;
        sP[kseg][1][cp] = a1;
        sP[kseg][2][cp] = a2;
        sP[kseg][3][cp] = a3;
        __syncthreads();

        // reduce: 4 rows x 64 col-pairs = 256 units = 1/thread
        float vx = 0.f, vy = 0.f;
        #pragma unroll
        for (int ks = 0; ks < 4; ++ks) {
            float px, py; upk2(sP[ks][rrow][tid & 63], px, py);
            vx += px; vy += py;
        }
        const int grow = row0 + rrow;
        if (phase == 0) {
            float am  = __ldg(g_amask + grow);
            float inv = __fdividef(1.0f, __ldg(g_denom + grow));
            float2 bb = __ldg((const float2*)(b2 + rc));
            sIn[rrow][rc]     = pk2(fmaf(bb.x, am, vx) * inv);
            sIn[rrow][rc + 1] = pk2(fmaf(bb.y, am, vy) * inv);
        } else if (phase == 1) {
            float2 bb = __ldg((const float2*)(bc1 + rc));
            sIn[rrow][rc]     = pk2(silu_h(0.5f * (vx + bb.x)));
            sIn[rrow][rc + 1] = pk2(silu_h(0.5f * (vy + bb.y)));
        } else {
            float2 bb = __ldg((const float2*)(bc2 + rc));
            *(float2*)(out + grow * Cv + rc) = make_float2(vx + bb.x, vy + bb.y);
        }
        __syncthreads();
    }
}

// ---------------------------------------------------------------------------
// Launch. Inputs: 0:h 1:adj 2:W1a 3:W1b 4:b1 5:W2 6:b2 7:Wc1 8:bc1 9:Wc2 10:bc2
// ---------------------------------------------------------------------------
extern "C" void kernel_launch(void* const* d_in, const int* in_sizes, int n_in,
                              void* d_out, int out_size)
{
    (void)in_sizes; (void)n_in; (void)out_size;
    const float* h   = (const float*)d_in[0];
    const float* adj = (const float*)d_in[1];

    k_pre <<<256, 256>>>(h, (const float*)d_in[2], (const float*)d_in[3],
                         (const float*)d_in[4]);
    k_main<<<256, 256>>>(adj);
    k_post<<<256, 256>>>((const float*)d_in[5], (const float*)d_in[6],
                         (const float*)d_in[7], (const float*)d_in[8],
                         (const float*)d_in[9], (const float*)d_in[10],
                         (float*)d_out);
}